// round 16
// baseline (speedup 1.0000x reference)
#include <cuda_runtime.h>
#include <cuda_fp16.h>
#include <cstdint>

// ---------------------------------------------------------------------------
// AttentionIn via legacy mma.sync fp16 (f32 accumulate), sm_103 base target
// out = concat(residual, q, k, v); q/k rotary on first 64 dims/head, v plain
// fp16 operands (10-bit mantissa == tf32 precision); GEMM at legacy HMMA floor.
// BK=64, 3-stage cp.async ring, one barrier per K-step.
// Residual copy folded into GEMM; prep fused into one launch.
// ---------------------------------------------------------------------------

#define TOKENS   8192
#define DMODEL   2048
#define NTOT     6144            // 3 mats * 16 heads * 128
#define DHEAD    128
#define SEQLEN   2048
#define ROT_DIM  64

#define BM 128
#define BN 128
#define BK 64
#define NSTAGE 3
#define LDH 72                   // smem row stride in halfs (36 words): conflict-free
#define A_H (BM * LDH)           // 9216 halfs
#define B_H (BN * LDH)           // 9216 halfs
#define STAGE_H (A_H + B_H)      // 18432 halfs = 36864 B
#define SMEM_BYTES (NSTAGE * STAGE_H * 2)   // 110592 B

#define RES_F4   (TOKENS * DMODEL / 4)      // 4,194,304 float4
#define NCTA     (48 * 64)                  // 3072 GEMM CTAs
#define RES_STRIDE (NCTA * 256)             // 786,432 threads

// fused prep kernel grid partition
#define PREP_CVT_BLKS  4096
#define PREP_W_BLKS    (192 * 64)           // 12288
#define PREP_SIN_BLKS  256
#define PREP_BLKS      (PREP_CVT_BLKS + PREP_W_BLKS + PREP_SIN_BLKS)  // 16640

// scratch (module-static device memory; no runtime allocation)
__device__ __half  g_xh[TOKENS * DMODEL];        // fp16 x
__device__ __half  g_wh[(size_t)NTOT * DMODEL];  // fp16 W, K-major [n][k]
__device__ float2  g_sincos[SEQLEN * 32];        // [pos][pair] -> (sin, cos)

// ---------------------------------------------------------------------------
__device__ __forceinline__ void cp_async16(void* smem_ptr, const void* gmem_ptr) {
    unsigned s = (unsigned)__cvta_generic_to_shared(smem_ptr);
    asm volatile("cp.async.cg.shared.global [%0], [%1], 16;\n" :: "r"(s), "l"(gmem_ptr));
}
__device__ __forceinline__ void cp_commit() {
    asm volatile("cp.async.commit_group;\n");
}
template <int N>
__device__ __forceinline__ void cp_wait() {
    asm volatile("cp.async.wait_group %0;\n" :: "n"(N));
}
__device__ __forceinline__ uint32_t h2_bits(__half2 h) {
    uint32_t u;
    __builtin_memcpy(&u, &h, sizeof(u));
    return u;
}
__device__ __forceinline__ void mma_f16(float (&d)[4], const uint32_t a0,
                                        const uint32_t a1, const uint32_t a2,
                                        const uint32_t a3, const uint32_t b0,
                                        const uint32_t b1) {
    asm volatile(
        "mma.sync.aligned.m16n8k16.row.col.f32.f16.f16.f32 "
        "{%0,%1,%2,%3}, {%4,%5,%6,%7}, {%8,%9}, {%0,%1,%2,%3};"
        : "+f"(d[0]), "+f"(d[1]), "+f"(d[2]), "+f"(d[3])
        : "r"(a0), "r"(a1), "r"(a2), "r"(a3), "r"(b0), "r"(b1));
}

// ---------------------------------------------------------------------------
// fused prep: blocks [0,4096) cvtx, [4096,16384) wprep, [16384,16640) sincos
// ---------------------------------------------------------------------------
__global__ void prep_kernel(const float4* __restrict__ x,
                            const float* __restrict__ WQ,
                            const float* __restrict__ WK,
                            const float* __restrict__ WV) {
    __shared__ float t[32][33];
    const int b   = blockIdx.x;
    const int tid = threadIdx.x;

    if (b < PREP_CVT_BLKS) {
        // x (f32) -> g_xh (fp16), grid-stride over RES_F4 float4s
        uint2* dst = reinterpret_cast<uint2*>(g_xh);
        const int stride = PREP_CVT_BLKS * 256;
        for (int i = b * 256 + tid; i < RES_F4; i += stride) {
            float4 v = x[i];
            __half2 h0 = __floats2half2_rn(v.x, v.y);
            __half2 h1 = __floats2half2_rn(v.z, v.w);
            dst[i] = make_uint2(h2_bits(h0), h2_bits(h1));
        }
    } else if (b < PREP_CVT_BLKS + PREP_W_BLKS) {
        // W[mat][head][k][nin] -> g_wh[(mat*16+head)*128 + nin][k], fp16
        const int b2 = b - PREP_CVT_BLKS;
        const int n0 = (b2 % 192) * 32;
        const int k0 = (b2 / 192) * 32;
        const int tx = tid & 31, ty = tid >> 5;   // 32 x 8
#pragma unroll
        for (int j = 0; j < 4; j++) {
            int n = n0 + tx;
            int k = k0 + ty + j * 8;
            int mat = n >> 11;
            int rest = n & 2047;                 // head*128 + nin
            const float* W = (mat == 0) ? WQ : (mat == 1) ? WK : WV;
            t[ty + j * 8][tx] =
                W[(size_t)(rest >> 7) * DMODEL * DHEAD + (size_t)k * DHEAD + (rest & 127)];
        }
        __syncthreads();
#pragma unroll
        for (int j = 0; j < 4; j++) {
            int n = n0 + ty + j * 8;
            int k = k0 + tx;
            g_wh[(size_t)n * DMODEL + k] = __float2half_rn(t[tx][ty + j * 8]);
        }
    } else {
        // sin/cos table: 2048 pos x 32 pairs
        int idx = (b - PREP_CVT_BLKS - PREP_W_BLKS) * 256 + tid;
        int pos = idx >> 5, i = idx & 31;
        float freq = powf(10000.0f, (float)i * (1.0f / 32.0f));
        float ang  = (float)pos / freq;
        g_sincos[idx] = make_float2(sinf(ang), cosf(ang));
    }
}

// ---------------------------------------------------------------------------
// GEMM: gridDim = (48 [mat*16+head], 64 [M tiles]), 256 threads, 8 warps (4m x 2n)
// Also copies its grid-stride share of the residual passthrough.
// ---------------------------------------------------------------------------
__global__ void __launch_bounds__(256, 2)
qkv_gemm_kernel(const float* __restrict__ bQ, const float* __restrict__ bK,
                const float* __restrict__ bV,
                const float4* __restrict__ res4,
                float* __restrict__ out) {
    extern __shared__ __half smem[];

    const int nb   = blockIdx.x;           // 0..47
    const int mb   = blockIdx.y;           // 0..63
    const int mat  = nb >> 4;              // 0=Q, 1=K, 2=V
    const int head = nb & 15;

    const __half* Ag = g_xh + (size_t)mb * BM * DMODEL;
    const __half* Bg = g_wh + (size_t)nb * BN * DMODEL;   // K-major [128 n][2048 k]
    const float* bsel = (mat == 0) ? bQ : (mat == 1) ? bK : bV;
    const float* bias = bsel + head * DHEAD;
    float* Og = out + (size_t)(mat + 1) * TOKENS * DMODEL + head * DHEAD;

    const bool do_rot = (mat < 2);         // rotary on Q/K only

    const int tid    = threadIdx.x;
    const int wid    = tid >> 5;
    const int lane   = tid & 31;
    const int warp_m = wid >> 1;           // 0..3 -> m offset *32
    const int warp_n = wid & 1;            // 0..1 -> n offset *64
    const int g      = lane >> 2;          // groupID
    const int c      = lane & 3;           // threadID_in_group

    float acc[2][8][4];
#pragma unroll
    for (int mi = 0; mi < 2; mi++)
#pragma unroll
        for (int ni = 0; ni < 8; ni++)
#pragma unroll
            for (int r = 0; r < 4; r++) acc[mi][ni][r] = 0.0f;

    // ---- stage loader: tiles [128 rows][64 k] fp16, stride LDH=72 halfs ----
    auto load_stage = [&](int buf, int k0) {
        __half* As = smem + buf * STAGE_H;
        __half* Bs = As + A_H;
#pragma unroll
        for (int i = 0; i < 4; i++) {          // A: 1024 x 16B segs
            int id = tid + i * 256;
            int r = id >> 3, s = id & 7;
            cp_async16(As + r * LDH + s * 8, Ag + (size_t)r * DMODEL + k0 + s * 8);
        }
#pragma unroll
        for (int i = 0; i < 4; i++) {          // B: 1024 x 16B segs
            int id = tid + i * 256;
            int r = id >> 3, s = id & 7;
            cp_async16(Bs + r * LDH + s * 8, Bg + (size_t)r * DMODEL + k0 + s * 8);
        }
        cp_commit();
    };

    const int KT = DMODEL / BK;   // 32
    load_stage(0, 0);             // group: stage 0
    load_stage(1, BK);            // group: stage 1

    // ---- residual passthrough: this CTA's grid-stride share (~1366 float4) ----
    // Overlaps the cp.async prologue; DRAM headroom inside the GEMM is ~90%.
    {
        float4* out4 = reinterpret_cast<float4*>(out);
        const int cta = mb * 48 + nb;          // 0..3071
        for (int i = cta * 256 + tid; i < RES_F4; i += RES_STRIDE)
            out4[i] = res4[i];
    }

    for (int kt = 0; kt < KT; kt++) {
        // Two groups pending here (kt, kt+1) except at the tail; wait_group 1
        // leaves <=1 pending -> stage kt is complete. Tail: wait<0>.
        if (kt + 1 < KT) cp_wait<1>();
        else             cp_wait<0>();
        // Single barrier: (a) stage-kt smem data visible CTA-wide,
        // (b) every warp finished compute(kt-1) -> buffer (kt+2)%3 free.
        __syncthreads();
        if (kt + 2 < KT) load_stage((kt + 2) % NSTAGE, (kt + 2) * BK);

        // word view: row stride 36 uint32 (LDH/2)
        const uint32_t* Aw =
            reinterpret_cast<const uint32_t*>(smem + (kt % NSTAGE) * STAGE_H);
        const uint32_t* Bw = Aw + A_H / 2;

#pragma unroll
        for (int ks = 0; ks < 4; ks++) {       // four k16 steps per BK=64
            const int kw = ks * 8;             // 8 words = 16 halfs
            uint32_t a[2][4];
#pragma unroll
            for (int mi = 0; mi < 2; mi++) {
                int r0 = warp_m * 32 + mi * 16 + g;
                a[mi][0] = Aw[r0 * 36 + kw + c];
                a[mi][1] = Aw[(r0 + 8) * 36 + kw + c];
                a[mi][2] = Aw[r0 * 36 + kw + c + 4];
                a[mi][3] = Aw[(r0 + 8) * 36 + kw + c + 4];
            }
            uint32_t b[8][2];
#pragma unroll
            for (int ni = 0; ni < 8; ni++) {
                int n = warp_n * 64 + ni * 8 + g;       // B row (K-major)
                b[ni][0] = Bw[n * 36 + kw + c];
                b[ni][1] = Bw[n * 36 + kw + c + 4];
            }
#pragma unroll
            for (int mi = 0; mi < 2; mi++)
#pragma unroll
                for (int ni = 0; ni < 8; ni++)
                    mma_f16(acc[mi][ni], a[mi][0], a[mi][1], a[mi][2], a[mi][3],
                            b[ni][0], b[ni][1]);
        }
    }

    // ---- epilogue: bias + rotary(Q,K only) + store ----
#pragma unroll
    for (int mi = 0; mi < 2; mi++) {
#pragma unroll
        for (int half = 0; half < 2; half++) {   // rows g / g+8
            int row = mb * BM + warp_m * 32 + mi * 16 + g + half * 8;  // token
            int pos = row & (SEQLEN - 1);
            float* orow = Og + (size_t)row * DMODEL;
            const float2* sct = g_sincos + pos * 32;
            int r0 = half * 2;   // acc regs {0,1} or {2,3}
#pragma unroll
            for (int ni = 0; ni < 8; ni++) {
                int e = warp_n * 64 + ni * 8 + c * 2;   // even column in head
                float v0 = acc[mi][ni][r0]     + bias[e];
                float v1 = acc[mi][ni][r0 + 1] + bias[e + 1];
                if (do_rot && e < ROT_DIM) {
                    float2 sc = sct[e >> 1];   // x=sin, y=cos
                    float o0 = v0 * sc.y - v1 * sc.x;
                    float o1 = v1 * sc.y + v0 * sc.x;
                    v0 = o0; v1 = o1;
                }
                *reinterpret_cast<float2*>(orow + e) = make_float2(v0, v1);
            }
        }
    }
}

// ---------------------------------------------------------------------------
extern "C" void kernel_launch(void* const* d_in, const int* in_sizes, int n_in,
                              void* d_out, int out_size) {
    const float* residual = (const float*)d_in[0];
    const float* x        = (const float*)d_in[1];
    const float* WQ       = (const float*)d_in[2];
    const float* WK       = (const float*)d_in[3];
    const float* WV       = (const float*)d_in[4];
    const float* bQ       = (const float*)d_in[5];
    const float* bK       = (const float*)d_in[6];
    const float* bV       = (const float*)d_in[7];
    float* out = (float*)d_out;

    // fused prep: fp16 x, transposed fp16 W (K-major), rotary table
    prep_kernel<<<PREP_BLKS, 256>>>((const float4*)x, WQ, WK, WV);

    // fused QKV GEMM + bias + rotary + residual passthrough
    cudaFuncSetAttribute(qkv_gemm_kernel,
                         cudaFuncAttributeMaxDynamicSharedMemorySize, SMEM_BYTES);
    dim3 grid(48, 64);
    qkv_gemm_kernel<<<grid, 256, SMEM_BYTES>>>(bQ, bK, bV,
                                               (const float4*)residual, out);
}